// round 15
// baseline (speedup 1.0000x reference)
#include <cuda_runtime.h>
#include <cuda_bf16.h>
#include <cstdint>
#include <math.h>

#define CS 1024
#define NH 16
#define HD 64

typedef unsigned int u32;

// ---------------- scratch (static device globals; no runtime allocation) ----
__device__ float g_g[1024 * 1024];
__device__ float g_z[16 * 1024 * 1024];   // [h][i][j]
__device__ float g_part[2][1024 * 1024];  // split-K partials for out GEMM

// bf16 hi/lo split operands for tensor-core GEMMs
__device__ __nv_bfloat16 g_s_hi[1024 * 1024],  g_s_lo[1024 * 1024];
__device__ __nv_bfloat16 g_ki_hi[1024 * 1024], g_ki_lo[1024 * 1024];
__device__ __nv_bfloat16 g_wq_hi[1024 * 1024], g_wq_lo[1024 * 1024];
__device__ __nv_bfloat16 g_wk_hi[1024 * 1024], g_wk_lo[1024 * 1024];
__device__ __nv_bfloat16 g_wv_hi[1024 * 1024], g_wv_lo[1024 * 1024];
__device__ __nv_bfloat16 g_wg_hi[1024 * 1024], g_wg_lo[1024 * 1024];
__device__ __nv_bfloat16 g_wo_hi[1024 * 1024], g_wo_lo[1024 * 1024];
__device__ __nv_bfloat16 g_ot_hi[1024 * 1024], g_ot_lo[1024 * 1024];
// q,k,v stored directly as bf16 hi/lo from projection epilogue
__device__ __nv_bfloat16 g_qh[1024 * 1024], g_ql[1024 * 1024];
__device__ __nv_bfloat16 g_kh[1024 * 1024], g_kl[1024 * 1024];
__device__ __nv_bfloat16 g_vh[1024 * 1024], g_vl[1024 * 1024];

// ---------------- helpers ---------------------------------------------------
__device__ __forceinline__ u32 smem_u32(const void* p) {
    u32 a;
    asm("{ .reg .u64 t; cvta.to.shared.u64 t, %1; cvt.u32.u64 %0, t; }" : "=r"(a) : "l"(p));
    return a;
}
__device__ __forceinline__ void ldm_x4(u32 addr, u32* r) {
    asm volatile("ldmatrix.sync.aligned.m8n8.x4.shared.b16 {%0,%1,%2,%3}, [%4];"
                 : "=r"(r[0]), "=r"(r[1]), "=r"(r[2]), "=r"(r[3]) : "r"(addr));
}
__device__ __forceinline__ void ldm_x4_t(u32 addr, u32* r) {
    asm volatile("ldmatrix.sync.aligned.m8n8.x4.trans.shared.b16 {%0,%1,%2,%3}, [%4];"
                 : "=r"(r[0]), "=r"(r[1]), "=r"(r[2]), "=r"(r[3]) : "r"(addr));
}
__device__ __forceinline__ void mma16816(float* c, const u32* a, const u32* b) {
    asm volatile(
        "mma.sync.aligned.m16n8k16.row.col.f32.bf16.bf16.f32 "
        "{%0,%1,%2,%3},{%4,%5,%6,%7},{%8,%9},{%0,%1,%2,%3};"
        : "+f"(c[0]), "+f"(c[1]), "+f"(c[2]), "+f"(c[3])
        : "r"(a[0]), "r"(a[1]), "r"(a[2]), "r"(a[3]), "r"(b[0]), "r"(b[1]));
}
__device__ __forceinline__ u32 pkbf2(__nv_bfloat16 a, __nv_bfloat16 b) {
    __nv_bfloat162 t = __halves2bfloat162(a, b);
    return *(u32*)&t;
}
__device__ __forceinline__ u32 prmt_hi(float a, float b) {
    u32 r;
    asm("prmt.b32 %0, %1, %2, 0x7632;"
        : "=r"(r) : "r"(__float_as_uint(a)), "r"(__float_as_uint(b)));
    return r;
}
__device__ __forceinline__ float trunc_hi(float a) {
    return __uint_as_float(__float_as_uint(a) & 0xFFFF0000u);
}
__device__ __forceinline__ void cpa16(u32 dst, const void* src) {
    asm volatile("cp.async.cg.shared.global [%0], [%1], 16;" :: "r"(dst), "l"(src));
}
#define CPA_COMMIT() asm volatile("cp.async.commit_group;" ::: "memory")
#define CPA_WAIT(n)  asm volatile("cp.async.wait_group %0;" :: "n"(n) : "memory")

// ---------------- fp32 -> bf16 hi/lo split ----------------------------------
__global__ __launch_bounds__(256) void split_kernel(const float* __restrict__ s,
                                                    const float* __restrict__ kin,
                                                    const float* __restrict__ wq,
                                                    const float* __restrict__ wk,
                                                    const float* __restrict__ wv,
                                                    const float* __restrict__ wg,
                                                    const float* __restrict__ wo) {
    const float* src;
    __nv_bfloat16 *dh, *dl;
    switch (blockIdx.y) {
        case 0: src = s;   dh = g_s_hi;  dl = g_s_lo;  break;
        case 1: src = kin; dh = g_ki_hi; dl = g_ki_lo; break;
        case 2: src = wq;  dh = g_wq_hi; dl = g_wq_lo; break;
        case 3: src = wk;  dh = g_wk_hi; dl = g_wk_lo; break;
        case 4: src = wv;  dh = g_wv_hi; dl = g_wv_lo; break;
        case 5: src = wg;  dh = g_wg_hi; dl = g_wg_lo; break;
        default: src = wo; dh = g_wo_hi; dl = g_wo_lo; break;
    }
    size_t i = ((size_t)blockIdx.x * 256 + threadIdx.x) * 4;
    float4 v = *(const float4*)(src + i);
    __nv_bfloat16 h0 = __float2bfloat16(v.x), h1 = __float2bfloat16(v.y);
    __nv_bfloat16 h2 = __float2bfloat16(v.z), h3 = __float2bfloat16(v.w);
    __nv_bfloat16 l0 = __float2bfloat16(v.x - __bfloat162float(h0));
    __nv_bfloat16 l1 = __float2bfloat16(v.y - __bfloat162float(h1));
    __nv_bfloat16 l2 = __float2bfloat16(v.z - __bfloat162float(h2));
    __nv_bfloat16 l3 = __float2bfloat16(v.w - __bfloat162float(h3));
    *(uint2*)(dh + i) = make_uint2(pkbf2(h0, h1), pkbf2(h2, h3));
    *(uint2*)(dl + i) = make_uint2(pkbf2(l0, l1), pkbf2(l2, l3));
}

// ---------------- pipelined HMMA GEMM tile: C[128,128] = A * B^T ------------
__device__ __forceinline__ void gemm_stage_ld(char* smem, int stage,
                                              const __nv_bfloat16* Ah,
                                              const __nv_bfloat16* Al,
                                              const __nv_bfloat16* Bh,
                                              const __nv_bfloat16* Bl,
                                              int bm0, int bn0, int kt, int tid) {
    const u32 sb = smem_u32(smem) + stage * 65536;
#pragma unroll
    for (int op = 0; op < 4; op++) {
        const __nv_bfloat16* src = (op == 0) ? Ah : (op == 1) ? Al : (op == 2) ? Bh : Bl;
        const int r0 = (op < 2) ? bm0 : bn0;
        const u32 d0 = sb + op * 16384;
#pragma unroll
        for (int u = 0; u < 4; u++) {
            int lin = tid + u * 256;
            int row = lin >> 3, ch = lin & 7;
            u32 sw = (u32)(row * 128) + ((u32)(ch ^ (row & 7)) << 4);
            cpa16(d0 + sw, src + (size_t)(r0 + row) * 1024 + kt * 64 + (ch << 3));
        }
    }
}

template <int MODE>
__device__ __forceinline__ void hmma_tile(const __nv_bfloat16* __restrict__ Ah,
                                          const __nv_bfloat16* __restrict__ Al,
                                          const __nv_bfloat16* __restrict__ Bh,
                                          const __nv_bfloat16* __restrict__ Bl,
                                          float* __restrict__ C,
                                          __nv_bfloat16* __restrict__ Ch,
                                          __nv_bfloat16* __restrict__ Cl,
                                          const float* __restrict__ bias,
                                          int bm0, int bn0, int kt0, int ktn) {
    extern __shared__ char smem[];
    const int tid = threadIdx.x;
    const int lane = tid & 31, wid = tid >> 5;
    const int wm = wid & 1, wn = wid >> 1;          // 2 x 4 warp grid
    const u32 sbase = smem_u32(smem);

    float acc[4][4][4];
#pragma unroll
    for (int mt = 0; mt < 4; mt++)
#pragma unroll
        for (int nt = 0; nt < 4; nt++)
#pragma unroll
            for (int e = 0; e < 4; e++) acc[mt][nt][e] = 0.f;

    gemm_stage_ld(smem, 0, Ah, Al, Bh, Bl, bm0, bn0, kt0, tid);
    CPA_COMMIT();

    for (int i = 0; i < ktn; i++) {
        if (i + 1 < ktn) {
            gemm_stage_ld(smem, (i + 1) & 1, Ah, Al, Bh, Bl, bm0, bn0, kt0 + i + 1, tid);
            CPA_COMMIT();
            CPA_WAIT(1);
        } else {
            CPA_WAIT(0);
        }
        __syncthreads();
        const u32 st = sbase + (u32)(i & 1) * 65536;

#pragma unroll
        for (int ks = 0; ks < 4; ks++) {
            u32 ah[4][4], al[4][4], bh[2][4], bl[2][4];
#pragma unroll
            for (int mt = 0; mt < 4; mt++) {
                int row = wm * 64 + mt * 16 + (lane & 15);
                int ch = ks * 2 + (lane >> 4);
                u32 addr = st + row * 128 + ((u32)(ch ^ (row & 7)) << 4);
                ldm_x4(addr, ah[mt]);
                ldm_x4(addr + 16384, al[mt]);
            }
#pragma unroll
            for (int nh = 0; nh < 2; nh++) {
                int row = wn * 32 + nh * 16 + (lane & 7) + ((lane >> 4) << 3);
                int ch = ks * 2 + ((lane >> 3) & 1);
                u32 addr = st + 32768 + row * 128 + ((u32)(ch ^ (row & 7)) << 4);
                ldm_x4(addr, bh[nh]);
                ldm_x4(addr + 16384, bl[nh]);
            }
#pragma unroll
            for (int mt = 0; mt < 4; mt++)
#pragma unroll
                for (int nt = 0; nt < 4; nt++)
                    mma16816(acc[mt][nt], ah[mt], &bh[nt >> 1][(nt & 1) * 2]);
#pragma unroll
            for (int mt = 0; mt < 4; mt++)
#pragma unroll
                for (int nt = 0; nt < 4; nt++)
                    mma16816(acc[mt][nt], ah[mt], &bl[nt >> 1][(nt & 1) * 2]);
#pragma unroll
            for (int mt = 0; mt < 4; mt++)
#pragma unroll
                for (int nt = 0; nt < 4; nt++)
                    mma16816(acc[mt][nt], al[mt], &bh[nt >> 1][(nt & 1) * 2]);
        }
        __syncthreads();
    }

#pragma unroll
    for (int mt = 0; mt < 4; mt++) {
        int r0 = bm0 + wm * 64 + mt * 16 + (lane >> 2);
#pragma unroll
        for (int nt = 0; nt < 4; nt++) {
            int c0 = bn0 + wn * 32 + nt * 8 + (lane & 3) * 2;
            float v0 = acc[mt][nt][0], v1 = acc[mt][nt][1];
            float v2 = acc[mt][nt][2], v3 = acc[mt][nt][3];
            if (MODE == 1) {
                float b0 = bias[c0], b1 = bias[c0 + 1];
                v0 += b0; v1 += b1; v2 += b0; v3 += b1;
            }
            if (MODE == 2) {
                v0 = 1.f / (1.f + __expf(-v0)); v1 = 1.f / (1.f + __expf(-v1));
                v2 = 1.f / (1.f + __expf(-v2)); v3 = 1.f / (1.f + __expf(-v3));
            }
            if (MODE == 0 || MODE == 2) {
                *(float2*)(C + (size_t)r0 * 1024 + c0) = make_float2(v0, v1);
                *(float2*)(C + (size_t)(r0 + 8) * 1024 + c0) = make_float2(v2, v3);
            } else {
                *(u32*)(Ch + (size_t)r0 * 1024 + c0) = prmt_hi(v0, v1);
                *(u32*)(Ch + (size_t)(r0 + 8) * 1024 + c0) = prmt_hi(v2, v3);
                *(u32*)(Cl + (size_t)r0 * 1024 + c0) =
                    pkbf2(__float2bfloat16(v0 - trunc_hi(v0)), __float2bfloat16(v1 - trunc_hi(v1)));
                *(u32*)(Cl + (size_t)(r0 + 8) * 1024 + c0) =
                    pkbf2(__float2bfloat16(v2 - trunc_hi(v2)), __float2bfloat16(v3 - trunc_hi(v3)));
            }
        }
    }
}

// ---------------- fused projections q,k,v,g (HMMA, pipelined) ---------------
__global__ __launch_bounds__(256) void proj_tc_kernel(const float* __restrict__ bq) {
    const int bm0 = blockIdx.y * 128, bn0 = blockIdx.x * 128;
    switch (blockIdx.z) {
        case 0: hmma_tile<1>(g_s_hi, g_s_lo, g_wq_hi, g_wq_lo, nullptr, g_qh, g_ql, bq, bm0, bn0, 0, 16); break;
        case 1: hmma_tile<3>(g_ki_hi, g_ki_lo, g_wk_hi, g_wk_lo, nullptr, g_kh, g_kl, nullptr, bm0, bn0, 0, 16); break;
        case 2: hmma_tile<3>(g_ki_hi, g_ki_lo, g_wv_hi, g_wv_lo, nullptr, g_vh, g_vl, nullptr, bm0, bn0, 0, 16); break;
        default: hmma_tile<2>(g_s_hi, g_s_lo, g_wg_hi, g_wg_lo, g_g, nullptr, nullptr, nullptr, bm0, bn0, 0, 16); break;
    }
}

// ---------------- output GEMM: out = (g*o) @ Wo^T (split-K2) ----------------
__global__ __launch_bounds__(256) void out_tc_kernel() {
    const int kz = blockIdx.z;
    hmma_tile<0>(g_ot_hi, g_ot_lo, g_wo_hi, g_wo_lo, g_part[kz], nullptr, nullptr, nullptr,
                 blockIdx.y * 128, blockIdx.x * 128, kz * 8, 8);
}
__global__ __launch_bounds__(256) void out_add_kernel(float* __restrict__ out) {
    size_t i = ((size_t)blockIdx.x * 256 + threadIdx.x) * 4;
    float4 a = *(const float4*)(g_part[0] + i);
    float4 b = *(const float4*)(g_part[1] + i);
    *(float4*)(out + i) = make_float4(a.x + b.x, a.y + b.y, a.z + b.z, a.w + b.w);
}

// ---------------- tensor-core pair-bias z[h][i][j] + mask -------------------
// z = bias[1M,128] @ Wz[128,16], 3-term bf16 split, in-register fp32->hi/lo.
// 64-row tiles -> 75.8 KB smem so z CTAs CO-RESIDE with proj (131 KB) on an SM
// (z is DRAM-bound, proj is tensor-bound; overlap requires smem coexistence).
// 1024 CTAs x 256 thr; 16 tiles of 64 pairs each, cp.async double-buffered.
// Warp w: row-group rg=w&3 (16 rows), head-tile nt=w>>2 (8 heads).
#define ZROW 132
#define ZT64 (64 * ZROW)
__device__ __forceinline__ void ztc_stage(u32 sb, int stage, const float* __restrict__ bias,
                                          size_t row0, int tid) {
    const u32 base = sb + (u32)stage * (ZT64 * 4);
#pragma unroll
    for (int u = 0; u < 8; u++) {
        int lin = tid + u * 256;
        int row = lin >> 5, c4 = lin & 31;
        cpa16(base + (u32)(row * ZROW + c4 * 4) * 4, bias + (row0 + row) * 128 + c4 * 4);
    }
}

__global__ __launch_bounds__(256) void z_kernel(const float* __restrict__ bias,
                                                const float* __restrict__ Wz,
                                                const float* __restrict__ mask) {
    extern __shared__ float zsm[];
    float* wz = zsm + 2 * ZT64;
    const int tid = threadIdx.x, lane = tid & 31, w = tid >> 5;
    const u32 sb = smem_u32(zsm);
    const size_t p0 = (size_t)blockIdx.x * 1024;

    for (int i = tid; i < 2048; i += 256) wz[i] = Wz[i];
    ztc_stage(sb, 0, bias, p0, tid);
    CPA_COMMIT();
    __syncthreads();   // wz visible

    // this warp's Wz B-fragments (n8k16, col-major): n = g within head-tile nt
    const int t = lane & 3, g = lane >> 2;
    const int rg = w & 3, nt = w >> 2;
    u32 bh[8][2], bl[8][2];
#pragma unroll
    for (int ks = 0; ks < 8; ks++) {
        int h = nt * 8 + g;
        int k0 = ks * 16 + 2 * t;
#pragma unroll
        for (int half = 0; half < 2; half++) {
            float w0 = wz[(k0 + half * 8) * 16 + h];
            float w1 = wz[(k0 + half * 8 + 1) * 16 + h];
            bh[ks][half] = prmt_hi(w0, w1);
            bl[ks][half] = pkbf2(__float2bfloat16(w0 - trunc_hi(w0)),
                                 __float2bfloat16(w1 - trunc_hi(w1)));
        }
    }

    for (int tile = 0; tile < 16; tile++) {
        if (tile + 1 < 16) {
            ztc_stage(sb, (tile + 1) & 1, bias, p0 + (size_t)(tile + 1) * 64, tid);
            CPA_COMMIT();
            CPA_WAIT(1);
        } else {
            CPA_WAIT(0);
        }
        __syncthreads();
        const float* buf = zsm + (tile & 1) * ZT64;

        float acc[4] = {0.f, 0.f, 0.f, 0.f};
        const int r0 = rg * 16 + g;
#pragma unroll
        for (int ks = 0; ks < 8; ks++) {
            int k0 = ks * 16 + 2 * t;
            u32 ah[4], al[4];
#pragma unroll
            for (int fi = 0; fi < 4; fi++) {
                int rr = r0 + ((fi & 1) << 3);     // a0:(r,k) a1:(r+8,k) a2:(r,k+8) a3:(r+8,k+8)
                int cc = k0 + ((fi >> 1) << 3);
                float2 f = *(const float2*)&buf[rr * ZROW + cc];
                ah[fi] = prmt_hi(f.x, f.y);
                al[fi] = pkbf2(__float2bfloat16(f.x - trunc_hi(f.x)),
                               __float2bfloat16(f.y - trunc_hi(f.y)));
            }
            mma16816(acc, ah, bh[ks]);
            mma16816(acc, ah, bl[ks]);
            mma16816(acc, al, bh[ks]);
        }

        // store (C frag rows r0, r0+8; cols nt*8 + 2t, +1) with mask folded in
        int jr = tile * 64 + r0;                   // == pair & 1023 (p0 mult of 1024)
        float m0 = (1.f - mask[jr]) * (-1000000.f);
        float m1 = (1.f - mask[jr + 8]) * (-1000000.f);
        size_t pr0 = p0 + (size_t)jr, pr1 = pr0 + 8;
        int hc = nt * 8 + 2 * t;
        g_z[(size_t)hc * 1048576 + pr0]       = acc[0] + m0;
        g_z[(size_t)(hc + 1) * 1048576 + pr0] = acc[1] + m0;
        g_z[(size_t)hc * 1048576 + pr1]       = acc[2] + m1;
        g_z[(size_t)(hc + 1) * 1048576 + pr1] = acc[3] + m1;
        __syncthreads();   // buffer free for restage
    }
}

// ---------------- HMMA flash attention (pipelined, BM=64, 2 CTA/SM) ---------
__device__ __forceinline__ void attn_ldkv(char* smc, int stage, int j0g, int h, int tid) {
    const u32 base = smem_u32(smc) + 16384 + stage * 32768;
#pragma unroll
    for (int u = 0; u < 4; u++) {
        int lin = tid + u * 128;
        int row = lin >> 3, ch = lin & 7;
        u32 sw = (u32)(row * 128) + ((u32)(ch ^ (row & 7)) << 4);
        size_t go = (size_t)(j0g + row) * 2048 + h * 128 + (ch << 4);
        cpa16(base + sw,         (const char*)g_kh + go);
        cpa16(base + 8192 + sw,  (const char*)g_kl + go);
        cpa16(base + 16384 + sw, (const char*)g_vh + go);
        cpa16(base + 24576 + sw, (const char*)g_vl + go);
    }
}

__global__ __launch_bounds__(128) void attn_kernel() {
    extern __shared__ char smc[];
    const int tid = threadIdx.x, lane = tid & 31, w = tid >> 5;
    const int h = blockIdx.y;
    const int i0 = blockIdx.x * 64;
    const u32 sb = smem_u32(smc);
    const u32 Qhs = sb;

#pragma unroll
    for (int u = 0; u < 4; u++) {
        int lin = tid + u * 128;
        int row = lin >> 3, ch = lin & 7;
        u32 sw16 = ((u32)(ch ^ (row & 7))) << 4;
        size_t go = (size_t)(i0 + row) * 2048 + h * 128 + (ch << 4);
        *(uint4*)(smc + row * 128 + sw16) = *(const uint4*)((const char*)g_qh + go);
        *(uint4*)(smc + 8192 + row * 128 + sw16) = *(const uint4*)((const char*)g_ql + go);
    }
    attn_ldkv(smc, 0, 0, h, tid);
    CPA_COMMIT();
    __syncthreads();

    u32 qh[4][4], ql[4][4];
    {
        int row = w * 16 + ((lane >> 3) & 1) * 8 + (lane & 7);
        u32 rbase = Qhs + row * 128;
#pragma unroll
        for (int kc = 0; kc < 4; kc++) {
            int ch = kc * 2 + (lane >> 4);
            u32 a = rbase + ((u32)(ch ^ (row & 7)) << 4);
            ldm_x4(a, qh[kc]);
            ldm_x4(a + 8192, ql[kc]);
        }
    }

    float m0 = -1e30f, m1 = -1e30f, l0 = 0.f, l1 = 0.f;
    float O[8][4];
#pragma unroll
    for (int nt = 0; nt < 8; nt++)
#pragma unroll
        for (int e = 0; e < 4; e++) O[nt][e] = 0.f;

    const float* zbase = g_z + (size_t)h * 1048576 +
                         (size_t)(i0 + w * 16 + (lane >> 2)) * 1024 + 2 * (lane & 3);

    for (int jt = 0; jt < 16; jt++) {
        const int j0g = jt * 64;
        if (jt + 1 < 16) {
            attn_ldkv(smc, (jt + 1) & 1, j0g + 64, h, tid);
            CPA_COMMIT();
            CPA_WAIT(1);
        } else {
            CPA_WAIT(0);
        }
        __syncthreads();
        const u32 Khs = sb + 16384 + (u32)(jt & 1) * 32768;
        const u32 Vhs = Khs + 16384;

        float acc[8][4];
#pragma unroll
        for (int nt = 0; nt < 8; nt++)
#pragma unroll
            for (int e = 0; e < 4; e++) acc[nt][e] = 0.f;

#pragma unroll
        for (int kc = 0; kc < 4; kc++) {
            u32 kbh[4][4], kbl[4][4];
#pragma unroll
            for (int jp = 0; jp < 4; jp++) {
                int row = jp * 16 + (lane >> 4) * 8 + (lane & 7);
                int ch = kc * 2 + ((lane >> 3) & 1);
                u32 a = Khs + row * 128 + ((u32)(ch ^ (row & 7)) << 4);
                ldm_x4(a, kbh[jp]);
                ldm_x4(a + 8192, kbl[jp]);
            }
#pragma unroll
            for (int jp = 0; jp < 4; jp++)
#pragma unroll
                for (int hh = 0; hh < 2; hh++)
                    mma16816(acc[jp * 2 + hh], qh[kc], &kbh[jp][hh * 2]);
#pragma unroll
            for (int jp = 0; jp < 4; jp++)
#pragma unroll
                for (int hh = 0; hh < 2; hh++)
                    mma16816(acc[jp * 2 + hh], qh[kc], &kbl[jp][hh * 2]);
#pragma unroll
            for (int jp = 0; jp < 4; jp++)
#pragma unroll
                for (int hh = 0; hh < 2; hh++)
                    mma16816(acc[jp * 2 + hh], ql[kc], &kbh[jp][hh * 2]);
        }

        const float* z0 = zbase + j0g;
        const float* z1 = z0 + 8192;
        float mx0 = -1e30f, mx1 = -1e30f;
#pragma unroll
        for (int nt = 0; nt < 8; nt++) {
            float2 za = *(const float2*)(z0 + nt * 8);
            float2 zb = *(const float2*)(z1 + nt * 8);
            acc[nt][0] = acc[nt][0] * 0.125f + za.x;
            acc[nt][1] = acc[nt][1] * 0.125f + za.y;
            acc[nt][2] = acc[nt][2] * 0.125f + zb.x;
            acc[nt][3] = acc[nt][3] * 0.125f + zb.y;
            mx0 = fmaxf(mx0, fmaxf(acc[nt][0], acc[nt][1]));
            mx1 = fmaxf(mx1, fmaxf(acc[nt][2], acc[nt][3]));
        }
        mx0 = fmaxf(mx0, __shfl_xor_sync(0xffffffffu, mx0, 1));
        mx0 = fmaxf(mx0, __shfl_xor_sync(0xffffffffu, mx0, 2));
        mx1 = fmaxf(mx1, __shfl_xor_sync(0xffffffffu, mx1, 1));
        mx1 = fmaxf(mx1, __shfl_xor_sync(0xffffffffu, mx1, 2));
        float mn0 = fmaxf(m0, mx0), mn1 = fmaxf(m1, mx1);
        float cr0 = __expf(m0 - mn0), cr1 = __expf(m1 - mn1);
        float rs0 = 0.f, rs1 = 0.f;
#pragma unroll
        for (int nt = 0; nt < 8; nt++) {
            acc[nt][0] = __expf(acc[nt][0] - mn0);
            acc[nt][1] = __expf(acc[nt][1] - mn0);
            acc[nt][2] = __expf(acc[nt][2] - mn1);
            acc[nt][3] = __expf(acc[nt][3] - mn1);
            rs0 += acc[nt][0] + acc[nt][1];
            rs1 += acc[nt][2] + acc[nt][3];
        }
        rs0 += __shfl_xor_sync(0xffffffffu, rs0, 1);
        rs0 += __shfl_xor_sync(0xffffffffu, rs0, 2);
        rs1 += __shfl_xor_sync(0xffffffffu, rs1, 1);
        rs1 += __shfl_xor_sync(0xffffffffu, rs1, 2);
        l0 = l0 * cr0 + rs0; m0 = mn0;
        l1 = l1 * cr1 + rs1; m1 = mn1;
#pragma unroll
        for (int nt = 0; nt < 8; nt++) {
            O[nt][0] *= cr0; O[nt][1] *= cr0;
            O[nt][2] *= cr1; O[nt][3] *= cr1;
        }

#pragma unroll
        for (int kc = 0; kc < 4; kc++) {
            u32 pah[4], pal[4];
            {
                float* pa = acc[kc * 2];
                float* pb = acc[kc * 2 + 1];
                pah[0] = prmt_hi(pa[0], pa[1]);
                pah[1] = prmt_hi(pa[2], pa[3]);
                pah[2] = prmt_hi(pb[0], pb[1]);
                pah[3] = prmt_hi(pb[2], pb[3]);
                pal[0] = prmt_hi(pa[0] - trunc_hi(pa[0]), pa[1] - trunc_hi(pa[1]));
                pal[1] = prmt_hi(pa[2] - trunc_hi(pa[2]), pa[3] - trunc_hi(pa[3]));
                pal[2] = prmt_hi(pb[0] - trunc_hi(pb[0]), pb[1] - trunc_hi(pb[1]));
                pal[3] = prmt_hi(pb[2] - trunc_hi(pb[2]), pb[3] - trunc_hi(pb[3]));
            }
            u32 vbh[4][4], vbl[4][4];
#pragma unroll
            for (int dp = 0; dp < 4; dp++) {
                int row = kc * 16 + ((lane >> 3) & 1) * 8 + (lane & 7);
                int ch = dp * 2 + (lane >> 4);
                u32 a = Vhs + row * 128 + ((u32)(ch ^ (row & 7)) << 4);
                ldm_x4_t(a, vbh[dp]);
                ldm_x4_t(a + 8192, vbl[dp]);
            }
#pragma unroll
            for (int dp = 0; dp < 4; dp++)
#pragma unroll
                for (int hh = 0; hh < 2; hh++)
                    mma16816(O[dp * 2 + hh], pah, &vbh[dp][hh * 2]);
#pragma unroll
            for (int dp = 0; dp < 4; dp++)
#pragma unroll
                for (int hh = 0; hh < 2; hh++)
                    mma16816(O[dp * 2 + hh], pal, &vbh[dp][hh * 2]);
#pragma unroll
            for (int dp = 0; dp < 4; dp++)
#pragma unroll
                for (int hh = 0; hh < 2; hh++)
                    mma16816(O[dp * 2 + hh], pah, &vbl[dp][hh * 2]);
        }
        __syncthreads();
    }

    l0 += __shfl_xor_sync(0xffffffffu, l0, 1);
    l0 += __shfl_xor_sync(0xffffffffu, l0, 2);
    l1 += __shfl_xor_sync(0xffffffffu, l1, 1);
    l1 += __shfl_xor_sync(0xffffffffu, l1, 2);
    l0 *= 0.25f; l1 *= 0.25f;   // rs was quad-reduced per tile; undo uniform 4x
    float inv0 = 1.f / l0, inv1 = 1.f / l1;
    const int rg0 = i0 + w * 16 + (lane >> 2);
    const int cb = h * 64 + 2 * (lane & 3);
#pragma unroll
    for (int nt = 0; nt < 8; nt++) {
        int c = cb + nt * 8;
        float2 ga = *(const float2*)(g_g + (size_t)rg0 * 1024 + c);
        float2 gb = *(const float2*)(g_g + (size_t)(rg0 + 8) * 1024 + c);
        float o0 = O[nt][0] * inv0 * ga.x;
        float o1 = O[nt][1] * inv0 * ga.y;
        float o2 = O[nt][2] * inv1 * gb.x;
        float o3 = O[nt][3] * inv1 * gb.y;
        *(u32*)(g_ot_hi + (size_t)rg0 * 1024 + c) = prmt_hi(o0, o1);
        *(u32*)(g_ot_hi + (size_t)(rg0 + 8) * 1024 + c) = prmt_hi(o2, o3);
        *(u32*)(g_ot_lo + (size_t)rg0 * 1024 + c) =
            pkbf2(__float2bfloat16(o0 - trunc_hi(o0)), __float2bfloat16(o1 - trunc_hi(o1)));
        *(u32*)(g_ot_lo + (size_t)(rg0 + 8) * 1024 + c) =
            pkbf2(__float2bfloat16(o2 - trunc_hi(o2)), __float2bfloat16(o3 - trunc_hi(o3)));
    }
}

// ---------------- launch ----------------------------------------------------
extern "C" void kernel_launch(void* const* d_in, const int* in_sizes, int n_in,
                              void* d_out, int out_size) {
    const float* s    = (const float*)d_in[0];
    const float* kin  = (const float*)d_in[1];
    const float* mask = (const float*)d_in[2];
    const float* bias = (const float*)d_in[3];
    const float* Wq   = (const float*)d_in[4];
    const float* bq   = (const float*)d_in[5];
    const float* Wk   = (const float*)d_in[6];
    const float* Wv   = (const float*)d_in[7];
    const float* Wg   = (const float*)d_in[8];
    const float* Wo   = (const float*)d_in[9];
    const float* Wz   = (const float*)d_in[10];
    float* out = (float*)d_out;

    static cudaStream_t zstream = nullptr;
    static cudaEvent_t ev_fork = nullptr, ev_join = nullptr;
    if (zstream == nullptr) {
        cudaStreamCreateWithFlags(&zstream, cudaStreamNonBlocking);
        cudaEventCreateWithFlags(&ev_fork, cudaEventDisableTiming);
        cudaEventCreateWithFlags(&ev_join, cudaEventDisableTiming);
    }

    cudaFuncSetAttribute(proj_tc_kernel, cudaFuncAttributeMaxDynamicSharedMemorySize, 131072);
    cudaFuncSetAttribute(out_tc_kernel,  cudaFuncAttributeMaxDynamicSharedMemorySize, 131072);
    cudaFuncSetAttribute(attn_kernel,    cudaFuncAttributeMaxDynamicSharedMemorySize, 81920);
    cudaFuncSetAttribute(z_kernel,       cudaFuncAttributeMaxDynamicSharedMemorySize, 75776);

    // fork: z (DRAM-paced HMMA, 75.8 KB smem) co-resident with proj (131 KB)
    cudaEventRecord(ev_fork, 0);
    cudaStreamWaitEvent(zstream, ev_fork, 0);
    z_kernel<<<1024, 256, 75776, zstream>>>(bias, Wz, mask);
    cudaEventRecord(ev_join, zstream);

    split_kernel<<<dim3(1024, 7), 256>>>(s, kin, Wq, Wk, Wv, Wg, Wo);
    proj_tc_kernel<<<dim3(8, 8, 4), 256, 131072>>>(bq);

    cudaStreamWaitEvent(0, ev_join, 0);
    attn_kernel<<<dim3(16, 16), 128, 81920>>>();
    out_tc_kernel<<<dim3(8, 8, 2), 256, 131072>>>();
    out_add_kernel<<<1024, 256>>>(out);
}